// round 16
// baseline (speedup 1.0000x reference)
#include <cuda_runtime.h>
#include <cuda_fp16.h>
#include <mma.h>
#include <math.h>
#include <stdint.h>

using namespace nvcuda;

#define NA 25000
#define NE 200000

// ---------------- static scratch ----------------
__device__ float g_dir[(size_t)NE * 3];
__device__ float g_phiS[(size_t)NE * 21];     // phi (gauss*fc, fc) fp32 per edge slot
__device__ int   g_js[NE];
__device__ int   g_eo[NE];
__device__ int   g_cnt[NA];
__device__ int   g_start[NA + 1];
__device__ int   g_cursor[NA];
__device__ float g_q[(size_t)NA * 128];
__device__ float g_x[(size_t)NA * 384];       // X2 result (fp32, feeds k_update)
__device__ __half g_xh[(size_t)NA * 384];     // X  result (fp16, feeds k_edge)
__device__ float g_muA[(size_t)NA * 384];
__device__ float g_muB[(size_t)NA * 384];
__device__ __half g_mm[(size_t)NA * 768];     // MUMIX result (fp16)
__device__ float g_s[(size_t)NA * 128];
__device__ __half g_fWe[3 * 21 * 384];        // fW slice per t (fb folded row 20)
// fp16 hi/lo activation buffers ([M, 2K]: hi cols [0,K), lo cols [K,2K))
__device__ __half g_qhl[(size_t)NA * 256];
__device__ __half g_hhl[(size_t)NA * 256];
__device__ __half g_ctxhl[(size_t)NA * 512];
__device__ __half g_muBhl[(size_t)NA * 768];
// fp16 transposed weights, K-duplicated ([N, 2K] = [W|W] per t)
__device__ __half g_WT1[3 * 128 * 256];
__device__ __half g_WT2[3 * 384 * 256];
__device__ __half g_WTmix[3 * 256 * 256];
__device__ __half g_WTm1[3 * 128 * 512];
__device__ __half g_WTm2[3 * 384 * 256];

// ---------------- helpers ----------------
__device__ __forceinline__ uint32_t smem_u32(const void* p) {
    uint32_t a;
    asm("{ .reg .u64 t; cvta.to.shared.u64 t, %1; cvt.u32.u64 %0, t; }" : "=r"(a) : "l"(p));
    return a;
}
__device__ __forceinline__ void cp16(void* dst, const void* src, int sz) {
    uint32_t d = smem_u32(dst);
    asm volatile("cp.async.cg.shared.global [%0], [%1], 16, %2;\n" :: "r"(d), "l"(src), "r"(sz));
}

// ---------------- 4-stage pipelined wmma GEMM: C = act(A @ W^T + bias) ----------------
// A: [M, K] fp16 (hi|lo packed in K).  W: [N, K] fp16 (K-duplicated).  Plain GEMM.
// CTA tile 128x128, 8 warps (4m x 2n), warp tile 32x64, BK=32.
// outmode: 0 = fp32 Cf [M,N]; 1 = hi|lo half Chl [M,2N]; 2 = plain half Chl [M,N].
#define TPAD 40
#define TSTG (128 * TPAD)
#define NSTG 4
#define SMEM_WG (NSTG * TSTG * 2 * 2)  // 81920 B
__global__ void __launch_bounds__(256, 2) k_wgemm(
    const __half* __restrict__ A, const __half* __restrict__ W,
    const float* __restrict__ bias, float* __restrict__ Cf,
    __half* __restrict__ Chl, int M, int K, int N, int outmode, int act) {
    extern __shared__ char smem[];
    __half* As = (__half*)smem;
    __half* Bs = As + NSTG * TSTG;
    int tid = threadIdx.x;
    int wid = tid >> 5;
    int m0 = blockIdx.x * 128, n0 = blockIdx.y * 128;
    int wm = wid & 3, wn = wid >> 2;

    wmma::fragment<wmma::accumulator, 16, 16, 16, float> acc[2][4];
#pragma unroll
    for (int i = 0; i < 2; i++)
#pragma unroll
        for (int j = 0; j < 4; j++) wmma::fill_fragment(acc[i][j], 0.0f);

    int ksteps = K >> 5;
    int r_ld = tid >> 2, c8 = (tid & 3) * 8;

    auto load_stage = [&](int step, int buf) {
        int ka = step * 32;
        __half* a_dst = As + buf * TSTG;
        __half* b_dst = Bs + buf * TSTG;
#pragma unroll
        for (int u = 0; u < 2; u++) {
            int r = r_ld + u * 64;
            int m = m0 + r;
            int mc = (m < M) ? m : (M - 1);
            cp16(a_dst + r * TPAD + c8, A + (size_t)mc * K + ka + c8, (m < M) ? 16 : 0);
            cp16(b_dst + r * TPAD + c8, W + (size_t)(n0 + r) * K + ka + c8, 16);
        }
        asm volatile("cp.async.commit_group;\n" ::: "memory");
    };

#pragma unroll
    for (int s = 0; s < NSTG - 1; s++) {
        if (s < ksteps) load_stage(s, s);
        else asm volatile("cp.async.commit_group;\n" ::: "memory");
    }
    for (int step = 0; step < ksteps; step++) {
        int buf = step & (NSTG - 1);
        asm volatile("cp.async.wait_group %0;\n" :: "n"(NSTG - 2) : "memory");
        __syncthreads();
        if (step + NSTG - 1 < ksteps) load_stage(step + NSTG - 1, (step + NSTG - 1) & (NSTG - 1));
        else asm volatile("cp.async.commit_group;\n" ::: "memory");
        const __half* Asb = As + buf * TSTG;
        const __half* Bsb = Bs + buf * TSTG;
#pragma unroll
        for (int kk = 0; kk < 32; kk += 16) {
            wmma::fragment<wmma::matrix_a, 16, 16, 16, __half, wmma::row_major> af[2];
            wmma::fragment<wmma::matrix_b, 16, 16, 16, __half, wmma::col_major> bf[4];
#pragma unroll
            for (int i = 0; i < 2; i++)
                wmma::load_matrix_sync(af[i], Asb + (wm * 32 + i * 16) * TPAD + kk, TPAD);
#pragma unroll
            for (int j = 0; j < 4; j++)
                wmma::load_matrix_sync(bf[j], Bsb + (wn * 64 + j * 16) * TPAD + kk, TPAD);
#pragma unroll
            for (int i = 0; i < 2; i++)
#pragma unroll
                for (int j = 0; j < 4; j++)
                    wmma::mma_sync(acc[i][j], af[i], bf[j], acc[i][j]);
        }
    }
    asm volatile("cp.async.wait_group 0;\n" ::: "memory");
    __syncthreads();

    // single-pass epilogue: full 128x128 fp32 staged in the (free) stage area
    float* stg = (float*)smem;
#pragma unroll
    for (int i = 0; i < 2; i++)
#pragma unroll
        for (int j = 0; j < 4; j++)
            wmma::store_matrix_sync(stg + (wm * 32 + i * 16) * 128 + wn * 64 + j * 16,
                                    acc[i][j], 128, wmma::mem_row_major);
    __syncthreads();
#pragma unroll
    for (int u = 0; u < 16; u++) {
        int idx = tid + u * 256;
        int r = idx >> 5, c4 = (idx & 31) * 4;
        int m = m0 + r;
        if (m >= M) continue;
        float4 v = *(float4*)&stg[r * 128 + c4];
        int n = n0 + c4;
        if (bias) {
            v.x += bias[n + 0]; v.y += bias[n + 1];
            v.z += bias[n + 2]; v.w += bias[n + 3];
        }
        if (act) {
            v.x = v.x / (1.0f + __expf(-v.x));
            v.y = v.y / (1.0f + __expf(-v.y));
            v.z = v.z / (1.0f + __expf(-v.z));
            v.w = v.w / (1.0f + __expf(-v.w));
        }
        if (outmode == 0) {
            *(float4*)(Cf + (size_t)m * N + n) = v;
        } else if (outmode == 2) {
            __half2 p0 = __half2(__float2half(v.x), __float2half(v.y));
            __half2 p1 = __half2(__float2half(v.z), __float2half(v.w));
            __half* pd = Chl + (size_t)m * N + n;
            *(__half2*)(pd + 0) = p0;
            *(__half2*)(pd + 2) = p1;
        } else {
            __half h0 = __float2half(v.x), h1 = __float2half(v.y);
            __half h2 = __float2half(v.z), h3 = __float2half(v.w);
            __half l0 = __float2half(v.x - __half2float(h0));
            __half l1 = __float2half(v.y - __half2float(h1));
            __half l2 = __float2half(v.z - __half2float(h2));
            __half l3 = __float2half(v.w - __half2float(h3));
            __half* ph = Chl + (size_t)m * 2 * N + n;
            *(__half2*)(ph + 0) = __half2(h0, h1);
            *(__half2*)(ph + 2) = __half2(h2, h3);
            __half* pl = Chl + (size_t)m * 2 * N + N + n;
            *(__half2*)(pl + 0) = __half2(l0, l1);
            *(__half2*)(pl + 2) = __half2(l2, l3);
        }
    }
}

// ---------------- prep kernels ----------------
// g_fWe[t][k][n]: fp16 fW slice for t (row 20 = fb)
__global__ void k_fwx(const float* __restrict__ fW, const float* __restrict__ fb) {
    int id = blockIdx.x * blockDim.x + threadIdx.x;
    if (id >= 1152) return;
    int t = id / 384, n = id % 384;
    for (int k = 0; k < 21; k++) {
        float v = (k < 20) ? fW[k * 1152 + t * 384 + n] : fb[t * 384 + n];
        g_fWe[(t * 21 + k) * 384 + n] = __float2half(v);
    }
}

// transpose [K,N] fp32 -> [N,2K] fp16 K-duplicated [W|W], for 3 t's
__global__ void k_wsplit(const float* __restrict__ src, __half* __restrict__ dst,
                         int K, int N) {
    int t = blockIdx.y;
    int id = blockIdx.x * 256 + threadIdx.x;
    if (id >= K * N) return;
    int k = id / N, n = id % N;
    float v = src[(size_t)t * K * N + (size_t)k * N + n];
    __half h = __float2half(v);
    size_t base = (size_t)t * N * 2 * K + (size_t)n * 2 * K;
    dst[base + k] = h;
    dst[base + K + k] = h;
}

__global__ void k_count(const int* __restrict__ idx_i) {
    int e = blockIdx.x * blockDim.x + threadIdx.x;
    if (e < NE) atomicAdd(&g_cnt[idx_i[e]], 1);
}

__global__ void k_scan() {
    __shared__ int sm[1024];
    __shared__ int carry_s;
    int tid = threadIdx.x;
    if (tid == 0) carry_s = 0;
    __syncthreads();
    for (int base = 0; base < NA; base += 1024) {
        int idx = base + tid;
        int v = (idx < NA) ? g_cnt[idx] : 0;
        sm[tid] = v;
        __syncthreads();
        for (int off = 1; off < 1024; off <<= 1) {
            int t = (tid >= off) ? sm[tid - off] : 0;
            __syncthreads();
            sm[tid] += t;
            __syncthreads();
        }
        int out = carry_s + sm[tid] - v;
        if (idx < NA) { g_start[idx] = out; g_cursor[idx] = out; }
        int tot = sm[1023];
        __syncthreads();
        if (tid == 0) carry_s += tot;
        __syncthreads();
    }
    if (tid == 0) g_start[NA] = carry_s;
}

__global__ void k_build(const float* __restrict__ pos,
                        const int* __restrict__ idx_i,
                        const int* __restrict__ idx_j) {
    int e = blockIdx.x * blockDim.x + threadIdx.x;
    if (e >= NE) return;
    int i = idx_i[e], j = idx_j[e];
    float r0 = pos[3 * j + 0] - pos[3 * i + 0];
    float r1 = pos[3 * j + 1] - pos[3 * i + 1];
    float r2 = pos[3 * j + 2] - pos[3 * i + 2];
    r0 = (fabsf(r0) < 1e-6f) ? 1e-6f : r0;
    r1 = (fabsf(r1) < 1e-6f) ? 1e-6f : r1;
    r2 = (fabsf(r2) < 1e-6f) ? 1e-6f : r2;
    float d = sqrtf(r0 * r0 + r1 * r1 + r2 * r2);
    float inv = 1.0f / d;
    float fc = (d < 5.0f) ? 0.5f * (cosf(0.628318530717959f * d) + 1.0f) : 0.0f;
    int slot = atomicAdd(&g_cursor[i], 1);
    g_js[slot] = j;
    g_eo[slot] = e;
    g_dir[3 * slot + 0] = r0 * inv;
    g_dir[3 * slot + 1] = r1 * inv;
    g_dir[3 * slot + 2] = r2 * inv;
    const float step = 5.0f / 19.0f;
    const float coeff = -7.22f;
    size_t pb = (size_t)slot * 21;
#pragma unroll
    for (int k = 0; k < 20; k++) {
        float df = d - (float)k * step;
        g_phiS[pb + k] = expf(coeff * df * df) * fc;
    }
    g_phiS[pb + 20] = fc;
}

__global__ void k_init_q(const int* __restrict__ z, const float* __restrict__ emb) {
    int n = blockIdx.x;
    int f = threadIdx.x;
    float v = emb[(size_t)z[n] * 128 + f];
    g_q[(size_t)n * 128 + f] = v;
    __half h = __float2half(v);
    g_qhl[(size_t)n * 256 + f] = h;
    g_qhl[(size_t)n * 256 + 128 + f] = __float2half(v - __half2float(h));
}

// ---------------- edge aggregation with fused filter (deterministic) ----------------
#define MAXD 512
__global__ void __launch_bounds__(128) k_edge(int t) {
    int i = blockIdx.x;
    int f = threadIdx.x;
    // per-thread filter-weight registers (3 x 21)
    float fwq[21], fwR[21], fwM[21];
    {
        const __half* fwt = g_fWe + t * 21 * 384;
#pragma unroll
        for (int k = 0; k < 21; k++) {
            fwq[k] = __half2float(fwt[k * 384 + f]);
            fwR[k] = __half2float(fwt[k * 384 + 128 + f]);
            fwM[k] = __half2float(fwt[k * 384 + 256 + f]);
        }
    }
    int s0 = g_start[i], s1 = g_start[i + 1];
    int L = s1 - s0;
    __shared__ int se[MAXD];
    __shared__ int ord[MAXD];
    bool srt = (L <= MAXD);
    if (srt && L > 0) {
        for (int a = f; a < L; a += 128) se[a] = g_eo[s0 + a];
        __syncthreads();
        for (int a = f; a < L; a += 128) {
            int my = se[a];
            int r = 0;
            for (int b = 0; b < L; b++) r += (se[b] < my);
            ord[r] = a;
        }
        __syncthreads();
    }
    float aq = 0.0f, m0 = 0.0f, m1 = 0.0f, m2 = 0.0f;
    for (int a = 0; a < L; a++) {
        int slot = s0 + (srt ? ord[a] : a);
        int j = g_js[slot];
        float d0 = g_dir[3 * slot + 0];
        float d1 = g_dir[3 * slot + 1];
        float d2 = g_dir[3 * slot + 2];
        // fused filter: 3 dot products of phi[21] with register weights
        float fq = 0.0f, fR = 0.0f, fM = 0.0f;
        const float* ph = g_phiS + (size_t)slot * 21;
#pragma unroll
        for (int k = 0; k < 21; k++) {
            float p = __ldg(ph + k);
            fq += p * fwq[k];
            fR += p * fwR[k];
            fM += p * fwM[k];
        }
        size_t xb = (size_t)j * 384;
        float xq = __half2float(g_xh[xb + f]);
        float xR = __half2float(g_xh[xb + 128 + f]);
        float xM = __half2float(g_xh[xb + 256 + f]);
        float mj0 = g_muA[xb + f];
        float mj1 = g_muA[xb + 128 + f];
        float mj2 = g_muA[xb + 256 + f];
        aq += fq * xq;
        float tR = fR * xR, tM = fM * xM;
        m0 += tR * d0 + tM * mj0;
        m1 += tR * d1 + tM * mj1;
        m2 += tR * d2 + tM * mj2;
    }
    size_t mb_ = (size_t)i * 384;
    g_q[(size_t)i * 128 + f] += aq;
    float b0 = g_muA[mb_ + f] + m0;
    float b1 = g_muA[mb_ + 128 + f] + m1;
    float b2 = g_muA[mb_ + 256 + f] + m2;
    g_muB[mb_ + f] = b0;
    g_muB[mb_ + 128 + f] = b1;
    g_muB[mb_ + 256 + f] = b2;
    size_t hb = (size_t)i * 768;
    __half h0 = __float2half(b0);
    __half h1 = __float2half(b1);
    __half h2 = __float2half(b2);
    g_muBhl[hb + f] = h0;
    g_muBhl[hb + 128 + f] = __float2half(b0 - __half2float(h0));
    g_muBhl[hb + 256 + f] = h1;
    g_muBhl[hb + 384 + f] = __float2half(b1 - __half2float(h1));
    g_muBhl[hb + 512 + f] = h2;
    g_muBhl[hb + 640 + f] = __float2half(b2 - __half2float(h2));
}

// ---------------- mixing elementwise ----------------
__global__ void k_ctx() {
    int n = blockIdx.x;
    int f = threadIdx.x;
    size_t mmb = (size_t)n * 768;
    float v0 = __half2float(g_mm[mmb + f]);
    float v1 = __half2float(g_mm[mmb + 256 + f]);
    float v2 = __half2float(g_mm[mmb + 512 + f]);
    float w0 = __half2float(g_mm[mmb + 128 + f]);
    float w1 = __half2float(g_mm[mmb + 384 + f]);
    float w2 = __half2float(g_mm[mmb + 640 + f]);
    float vn = sqrtf(v0 * v0 + v1 * v1 + v2 * v2 + 1e-8f);
    float s = v0 * w0 + v1 * w1 + v2 * w2;
    float qv = g_q[(size_t)n * 128 + f];
    size_t cb = (size_t)n * 512;
    __half qh = __float2half(qv);
    __half vh = __float2half(vn);
    g_ctxhl[cb + f] = qh;
    g_ctxhl[cb + 128 + f] = vh;
    g_ctxhl[cb + 256 + f] = __float2half(qv - __half2float(qh));
    g_ctxhl[cb + 384 + f] = __float2half(vn - __half2float(vh));
    g_s[(size_t)n * 128 + f] = s;
}

__global__ void k_update() {
    int n = blockIdx.x;
    int f = threadIdx.x;
    size_t xb = (size_t)n * 384;
    float dq  = g_x[xb + f];
    float dmc = g_x[xb + 128 + f];
    float dqm = g_x[xb + 256 + f];
    float qn = g_q[(size_t)n * 128 + f] + dq + dqm * g_s[(size_t)n * 128 + f];
    g_q[(size_t)n * 128 + f] = qn;
    __half qh = __float2half(qn);
    g_qhl[(size_t)n * 256 + f] = qh;
    g_qhl[(size_t)n * 256 + 128 + f] = __float2half(qn - __half2float(qh));
    size_t mmb = (size_t)n * 768;
    g_muA[xb + f]       = g_muB[xb + f]       + dmc * __half2float(g_mm[mmb + 128 + f]);
    g_muA[xb + 128 + f] = g_muB[xb + 128 + f] + dmc * __half2float(g_mm[mmb + 384 + f]);
    g_muA[xb + 256 + f] = g_muB[xb + 256 + f] + dmc * __half2float(g_mm[mmb + 640 + f]);
}

// ---------------- launcher ----------------
extern "C" void kernel_launch(void* const* d_in, const int* in_sizes, int n_in,
                              void* d_out, int out_size) {
    const int*   z     = (const int*)d_in[0];
    const float* pos   = (const float*)d_in[1];
    const int*   idx_i = (const int*)d_in[2];
    const int*   idx_j = (const int*)d_in[3];
    const float* emb   = (const float*)d_in[4];
    const float* fW    = (const float*)d_in[5];
    const float* fb    = (const float*)d_in[6];
    const float* iW1   = (const float*)d_in[7];
    const float* ib1   = (const float*)d_in[8];
    const float* iW2   = (const float*)d_in[9];
    const float* ib2   = (const float*)d_in[10];
    const float* mWmix = (const float*)d_in[11];
    const float* mW1   = (const float*)d_in[12];
    const float* mb1   = (const float*)d_in[13];
    const float* mW2   = (const float*)d_in[14];
    const float* mb2   = (const float*)d_in[15];
    float* out = (float*)d_out;

    cudaFuncSetAttribute(k_wgemm, cudaFuncAttributeMaxDynamicSharedMemorySize, SMEM_WG);

    void *p_cnt, *p_muA, *p_q, *p_x, *p_xh, *p_mm;
    void *p_qhl, *p_hhl, *p_ctxhl, *p_muBhl;
    void *p_WT1, *p_WT2, *p_WTmix, *p_WTm1, *p_WTm2;
    cudaGetSymbolAddress(&p_cnt, g_cnt);
    cudaGetSymbolAddress(&p_muA, g_muA);
    cudaGetSymbolAddress(&p_q, g_q);
    cudaGetSymbolAddress(&p_x, g_x);
    cudaGetSymbolAddress(&p_xh, g_xh);
    cudaGetSymbolAddress(&p_mm, g_mm);
    cudaGetSymbolAddress(&p_qhl, g_qhl);
    cudaGetSymbolAddress(&p_hhl, g_hhl);
    cudaGetSymbolAddress(&p_ctxhl, g_ctxhl);
    cudaGetSymbolAddress(&p_muBhl, g_muBhl);
    cudaGetSymbolAddress(&p_WT1, g_WT1);
    cudaGetSymbolAddress(&p_WT2, g_WT2);
    cudaGetSymbolAddress(&p_WTmix, g_WTmix);
    cudaGetSymbolAddress(&p_WTm1, g_WTm1);
    cudaGetSymbolAddress(&p_WTm2, g_WTm2);

    const __half* qhl = (const __half*)p_qhl;
    const __half* hhl = (const __half*)p_hhl;
    const __half* ctxhl = (const __half*)p_ctxhl;
    const __half* muBhl = (const __half*)p_muBhl;

    int ga = (NA + 127) / 128;       // 196
    int gm = (NA * 3 + 127) / 128;   // 586

    // ---- prep, ordered so the flagship GEMM is launch #6 (ncu -s 5 -c 1) ----
    cudaMemsetAsync(p_cnt, 0, NA * sizeof(int));                       // 1
    cudaMemsetAsync(p_muA, 0, (size_t)NA * 384 * sizeof(float));       // 2
    k_init_q<<<NA, 128>>>(z, emb);                                     // 3
    k_wsplit<<<dim3((128 * 128 + 255) / 256, 3), 256>>>(iW1, (__half*)p_WT1, 128, 128);   // 4
    k_wsplit<<<dim3((128 * 384 + 255) / 256, 3), 256>>>(iW2, (__half*)p_WT2, 128, 384);   // 5
    // H1(t=0): launch #6 -> profiled
    k_wgemm<<<dim3(ga, 1), 256, SMEM_WG>>>(
        qhl, (const __half*)p_WT1, ib1, nullptr, (__half*)p_hhl, NA, 256, 128, 1, 1);
    k_wsplit<<<dim3((128 * 256 + 255) / 256, 3), 256>>>(mWmix, (__half*)p_WTmix, 128, 256);
    k_wsplit<<<dim3((256 * 128 + 255) / 256, 3), 256>>>(mW1, (__half*)p_WTm1, 256, 128);
    k_wsplit<<<dim3((128 * 384 + 255) / 256, 3), 256>>>(mW2, (__half*)p_WTm2, 128, 384);
    k_fwx<<<(1152 + 127) / 128, 128>>>(fW, fb);
    k_count<<<(NE + 255) / 256, 256>>>(idx_i);
    k_scan<<<1, 1024>>>();
    k_build<<<(NE + 127) / 128, 128>>>(pos, idx_i, idx_j);

    for (int t = 0; t < 3; t++) {
        if (t > 0) {
            k_wgemm<<<dim3(ga, 1), 256, SMEM_WG>>>(
                qhl, (const __half*)p_WT1 + (size_t)t * 128 * 256,
                ib1 + t * 128, nullptr, (__half*)p_hhl, NA, 256, 128, 1, 1);
        }
        // X = H1 @ iW2 + ib2 -> g_xh (fp16 plain)
        k_wgemm<<<dim3(ga, 3), 256, SMEM_WG>>>(
            hhl, (const __half*)p_WT2 + (size_t)t * 384 * 256,
            ib2 + t * 384, nullptr, (__half*)p_xh, NA, 256, 384, 2, 0);
        // edge aggregation with fused filter
        k_edge<<<NA, 128>>>(t);
        // MUMIX = muB @ mWmix -> g_mm (fp16 plain)
        k_wgemm<<<dim3(gm, 2), 256, SMEM_WG>>>(
            muBhl, (const __half*)p_WTmix + (size_t)t * 256 * 256,
            nullptr, nullptr, (__half*)p_mm, NA * 3, 256, 256, 2, 0);
        k_ctx<<<NA, 128>>>();
        // H2 = silu(ctx @ mW1 + mb1) -> hhl   (K=512 packed)
        k_wgemm<<<dim3(ga, 1), 256, SMEM_WG>>>(
            ctxhl, (const __half*)p_WTm1 + (size_t)t * 128 * 512,
            mb1 + t * 128, nullptr, (__half*)p_hhl, NA, 512, 128, 1, 1);
        // X2 = H2 @ mW2 + mb2 -> g_x (fp32)
        k_wgemm<<<dim3(ga, 3), 256, SMEM_WG>>>(
            hhl, (const __half*)p_WTm2 + (size_t)t * 384 * 256,
            mb2 + t * 384, (float*)p_x, nullptr, NA, 256, 384, 0, 0);
        k_update<<<NA, 128>>>();
    }

    cudaMemcpyAsync(out, p_q, (size_t)NA * 128 * sizeof(float), cudaMemcpyDeviceToDevice);
    cudaMemcpyAsync(out + (size_t)NA * 128, p_muA, (size_t)NA * 384 * sizeof(float),
                    cudaMemcpyDeviceToDevice);
}

// round 17
// speedup vs baseline: 1.0838x; 1.0838x over previous
#include <cuda_runtime.h>
#include <cuda_fp16.h>
#include <mma.h>
#include <math.h>
#include <stdint.h>

using namespace nvcuda;

#define NA 25000
#define NE 200000

// ---------------- static scratch ----------------
__device__ float g_dir[(size_t)NE * 3];
__device__ int   g_js[NE];
__device__ int   g_eo[NE];
__device__ int   g_cnt[NA];
__device__ int   g_start[NA + 1];
__device__ int   g_cursor[NA];
__device__ float g_q[(size_t)NA * 128];
__device__ float g_x[(size_t)NA * 384];       // X2 result (fp32, feeds k_update)
__device__ __half g_xh[(size_t)NA * 384];     // X  result (fp16, feeds k_edge)
__device__ float g_muA[(size_t)NA * 384];
__device__ __half g_muAh[(size_t)NA * 384];   // fp16 mirror of muA for j-gather
__device__ float g_muB[(size_t)NA * 384];
__device__ __half g_mm[(size_t)NA * 768];     // MUMIX result (fp16)
__device__ float g_s[(size_t)NA * 128];
__device__ __half g_filth[(size_t)NE * 384];  // FILT result (fp16)
// fp16 hi/lo activation buffers ([M, 2K]: hi cols [0,K), lo cols [K,2K))
__device__ __half g_qhl[(size_t)NA * 256];
__device__ __half g_hhl[(size_t)NA * 256];
__device__ __half g_ctxhl[(size_t)NA * 512];
__device__ __half g_muBhl[(size_t)NA * 768];
// FILT operands: A'=[phi_hi(21)|phi_lo(21)|0] K=64, W'=[W|W|0]
__device__ __half g_phiHL[(size_t)NE * 64];
__device__ __half g_fWXhl[1152 * 64];
// fp16 transposed weights, K-duplicated ([N, 2K] = [W|W] per t)
__device__ __half g_WT1[3 * 128 * 256];
__device__ __half g_WT2[3 * 384 * 256];
__device__ __half g_WTmix[3 * 256 * 256];
__device__ __half g_WTm1[3 * 128 * 512];
__device__ __half g_WTm2[3 * 384 * 256];

// ---------------- helpers ----------------
__device__ __forceinline__ uint32_t smem_u32(const void* p) {
    uint32_t a;
    asm("{ .reg .u64 t; cvta.to.shared.u64 t, %1; cvt.u32.u64 %0, t; }" : "=r"(a) : "l"(p));
    return a;
}
__device__ __forceinline__ void cp16(void* dst, const void* src, int sz) {
    uint32_t d = smem_u32(dst);
    asm volatile("cp.async.cg.shared.global [%0], [%1], 16, %2;\n" :: "r"(d), "l"(src), "r"(sz));
}

// ---------------- 3-stage pipelined wmma GEMM: C = act(A @ W^T + bias) ----------------
// A: [M, K] fp16 (hi|lo packed in K).  W: [N, K] fp16 (K-duplicated).  Plain GEMM.
// CTA tile 128x64, 128 threads = 4 warps, warp tile 32x64, BK=32, NSTG=3.
// outmode: 0 = fp32 Cf [M,N]; 1 = hi|lo half Chl [M,2N]; 2 = plain half Chl [M,N].
#define TPAD 40
#define ASTG (128 * TPAD)
#define BSTG (64 * TPAD)
#define NSTG 3
#define SMEM_WG (NSTG * (ASTG + BSTG) * 2)  // 46080 B
__global__ void __launch_bounds__(128, 4) k_wgemm(
    const __half* __restrict__ A, const __half* __restrict__ W,
    const float* __restrict__ bias, float* __restrict__ Cf,
    __half* __restrict__ Chl, int M, int K, int N, int outmode, int act) {
    extern __shared__ char smem[];
    __half* As = (__half*)smem;                    // [NSTG][ASTG]
    __half* Bs = As + NSTG * ASTG;                 // [NSTG][BSTG]
    int tid = threadIdx.x;
    int wm = tid >> 5;                             // warp id = m-slice
    int m0 = blockIdx.x * 128, n0 = blockIdx.y * 64;

    wmma::fragment<wmma::accumulator, 16, 16, 16, float> acc[2][4];
#pragma unroll
    for (int i = 0; i < 2; i++)
#pragma unroll
        for (int j = 0; j < 4; j++) wmma::fill_fragment(acc[i][j], 0.0f);

    int ksteps = K >> 5;

    auto load_stage = [&](int step, int buf) {
        int ka = step * 32;
        __half* a_dst = As + buf * ASTG;
        __half* b_dst = Bs + buf * BSTG;
#pragma unroll
        for (int u = 0; u < 4; u++) {              // A: 512 chunks / 128 thr
            int c = tid + u * 128;
            int r = c >> 2, col8 = (c & 3) * 8;
            int m = m0 + r;
            int mc = (m < M) ? m : (M - 1);
            cp16(a_dst + r * TPAD + col8, A + (size_t)mc * K + ka + col8, (m < M) ? 16 : 0);
        }
#pragma unroll
        for (int u = 0; u < 2; u++) {              // B: 256 chunks / 128 thr
            int c = tid + u * 128;
            int r = c >> 2, col8 = (c & 3) * 8;
            cp16(b_dst + r * TPAD + col8, W + (size_t)(n0 + r) * K + ka + col8, 16);
        }
        asm volatile("cp.async.commit_group;\n" ::: "memory");
    };

#pragma unroll
    for (int s = 0; s < NSTG - 1; s++) {
        if (s < ksteps) load_stage(s, s);
        else asm volatile("cp.async.commit_group;\n" ::: "memory");
    }
    for (int step = 0; step < ksteps; step++) {
        int buf = step % NSTG;
        asm volatile("cp.async.wait_group %0;\n" :: "n"(NSTG - 2) : "memory");
        __syncthreads();
        if (step + NSTG - 1 < ksteps) load_stage(step + NSTG - 1, (step + NSTG - 1) % NSTG);
        else asm volatile("cp.async.commit_group;\n" ::: "memory");
        const __half* Asb = As + buf * ASTG;
        const __half* Bsb = Bs + buf * BSTG;
#pragma unroll
        for (int kk = 0; kk < 32; kk += 16) {
            wmma::fragment<wmma::matrix_a, 16, 16, 16, __half, wmma::row_major> af[2];
            wmma::fragment<wmma::matrix_b, 16, 16, 16, __half, wmma::col_major> bf[4];
#pragma unroll
            for (int i = 0; i < 2; i++)
                wmma::load_matrix_sync(af[i], Asb + (wm * 32 + i * 16) * TPAD + kk, TPAD);
#pragma unroll
            for (int j = 0; j < 4; j++)
                wmma::load_matrix_sync(bf[j], Bsb + (j * 16) * TPAD + kk, TPAD);
#pragma unroll
            for (int i = 0; i < 2; i++)
#pragma unroll
                for (int j = 0; j < 4; j++)
                    wmma::mma_sync(acc[i][j], af[i], bf[j], acc[i][j]);
        }
    }
    asm volatile("cp.async.wait_group 0;\n" ::: "memory");
    __syncthreads();

    // epilogue: stage 128x64 fp32 (32KB) in the stage area
    float* stg = (float*)smem;
#pragma unroll
    for (int i = 0; i < 2; i++)
#pragma unroll
        for (int j = 0; j < 4; j++)
            wmma::store_matrix_sync(stg + (wm * 32 + i * 16) * 64 + j * 16,
                                    acc[i][j], 64, wmma::mem_row_major);
    __syncthreads();
#pragma unroll
    for (int u = 0; u < 16; u++) {
        int idx = tid + u * 128;
        int r = idx >> 4, c4 = (idx & 15) * 4;
        int m = m0 + r;
        if (m >= M) continue;
        float4 v = *(float4*)&stg[r * 64 + c4];
        int n = n0 + c4;
        if (bias) {
            v.x += bias[n + 0]; v.y += bias[n + 1];
            v.z += bias[n + 2]; v.w += bias[n + 3];
        }
        if (act) {
            v.x = v.x / (1.0f + __expf(-v.x));
            v.y = v.y / (1.0f + __expf(-v.y));
            v.z = v.z / (1.0f + __expf(-v.z));
            v.w = v.w / (1.0f + __expf(-v.w));
        }
        if (outmode == 0) {
            *(float4*)(Cf + (size_t)m * N + n) = v;
        } else if (outmode == 2) {
            __half2 p0 = __half2(__float2half(v.x), __float2half(v.y));
            __half2 p1 = __half2(__float2half(v.z), __float2half(v.w));
            __half* pd = Chl + (size_t)m * N + n;
            *(__half2*)(pd + 0) = p0;
            *(__half2*)(pd + 2) = p1;
        } else {
            __half h0 = __float2half(v.x), h1 = __float2half(v.y);
            __half h2 = __float2half(v.z), h3 = __float2half(v.w);
            __half l0 = __float2half(v.x - __half2float(h0));
            __half l1 = __float2half(v.y - __half2float(h1));
            __half l2 = __float2half(v.z - __half2float(h2));
            __half l3 = __float2half(v.w - __half2float(h3));
            __half* ph = Chl + (size_t)m * 2 * N + n;
            *(__half2*)(ph + 0) = __half2(h0, h1);
            *(__half2*)(ph + 2) = __half2(h2, h3);
            __half* pl = Chl + (size_t)m * 2 * N + N + n;
            *(__half2*)(pl + 0) = __half2(l0, l1);
            *(__half2*)(pl + 2) = __half2(l2, l3);
        }
    }
}

// ---------------- prep kernels ----------------
// W' rows [1152,64]: cols [0,21)=W, [21,42)=W, [42,64)=0 (fb folded at k=20)
__global__ void k_fwx(const float* __restrict__ fW, const float* __restrict__ fb) {
    int n = blockIdx.x * blockDim.x + threadIdx.x;
    if (n >= 1152) return;
    for (int k = 0; k < 21; k++) {
        float v = (k < 20) ? fW[k * 1152 + n] : fb[n];
        __half h = __float2half(v);
        g_fWXhl[n * 64 + k] = h;
        g_fWXhl[n * 64 + 21 + k] = h;
    }
    for (int k = 42; k < 64; k++) g_fWXhl[n * 64 + k] = __float2half(0.0f);
}

// transpose [K,N] fp32 -> [N,2K] fp16 K-duplicated [W|W], for 3 t's
__global__ void k_wsplit(const float* __restrict__ src, __half* __restrict__ dst,
                         int K, int N) {
    int t = blockIdx.y;
    int id = blockIdx.x * 256 + threadIdx.x;
    if (id >= K * N) return;
    int k = id / N, n = id % N;
    float v = src[(size_t)t * K * N + (size_t)k * N + n];
    __half h = __float2half(v);
    size_t base = (size_t)t * N * 2 * K + (size_t)n * 2 * K;
    dst[base + k] = h;
    dst[base + K + k] = h;
}

__global__ void k_count(const int* __restrict__ idx_i) {
    int e = blockIdx.x * blockDim.x + threadIdx.x;
    if (e < NE) atomicAdd(&g_cnt[idx_i[e]], 1);
}

__global__ void k_scan() {
    __shared__ int sm[1024];
    __shared__ int carry_s;
    int tid = threadIdx.x;
    if (tid == 0) carry_s = 0;
    __syncthreads();
    for (int base = 0; base < NA; base += 1024) {
        int idx = base + tid;
        int v = (idx < NA) ? g_cnt[idx] : 0;
        sm[tid] = v;
        __syncthreads();
        for (int off = 1; off < 1024; off <<= 1) {
            int t = (tid >= off) ? sm[tid - off] : 0;
            __syncthreads();
            sm[tid] += t;
            __syncthreads();
        }
        int out = carry_s + sm[tid] - v;
        if (idx < NA) { g_start[idx] = out; g_cursor[idx] = out; }
        int tot = sm[1023];
        __syncthreads();
        if (tid == 0) carry_s += tot;
        __syncthreads();
    }
    if (tid == 0) g_start[NA] = carry_s;
}

// A' rows [E,64]: [phi_hi(21)|phi_lo(21)|0], fcut folded at k=20
__global__ void k_build(const float* __restrict__ pos,
                        const int* __restrict__ idx_i,
                        const int* __restrict__ idx_j) {
    int e = blockIdx.x * blockDim.x + threadIdx.x;
    if (e >= NE) return;
    int i = idx_i[e], j = idx_j[e];
    float r0 = pos[3 * j + 0] - pos[3 * i + 0];
    float r1 = pos[3 * j + 1] - pos[3 * i + 1];
    float r2 = pos[3 * j + 2] - pos[3 * i + 2];
    r0 = (fabsf(r0) < 1e-6f) ? 1e-6f : r0;
    r1 = (fabsf(r1) < 1e-6f) ? 1e-6f : r1;
    r2 = (fabsf(r2) < 1e-6f) ? 1e-6f : r2;
    float d = sqrtf(r0 * r0 + r1 * r1 + r2 * r2);
    float inv = 1.0f / d;
    float fc = (d < 5.0f) ? 0.5f * (cosf(0.628318530717959f * d) + 1.0f) : 0.0f;
    int slot = atomicAdd(&g_cursor[i], 1);
    g_js[slot] = j;
    g_eo[slot] = e;
    g_dir[3 * slot + 0] = r0 * inv;
    g_dir[3 * slot + 1] = r1 * inv;
    g_dir[3 * slot + 2] = r2 * inv;
    const float step = 5.0f / 19.0f;
    const float coeff = -7.22f;
    size_t pb = (size_t)slot * 64;
    for (int k = 0; k < 21; k++) {
        float v;
        if (k < 20) {
            float df = d - (float)k * step;
            v = expf(coeff * df * df) * fc;
        } else {
            v = fc;
        }
        __half h = __float2half(v);
        g_phiHL[pb + k] = h;
        g_phiHL[pb + 21 + k] = __float2half(v - __half2float(h));
    }
    for (int k = 42; k < 64; k++) g_phiHL[pb + k] = __float2half(0.0f);
}

__global__ void k_init_q(const int* __restrict__ z, const float* __restrict__ emb) {
    int n = blockIdx.x;
    int f = threadIdx.x;
    float v = emb[(size_t)z[n] * 128 + f];
    g_q[(size_t)n * 128 + f] = v;
    __half h = __float2half(v);
    g_qhl[(size_t)n * 256 + f] = h;
    g_qhl[(size_t)n * 256 + 128 + f] = __float2half(v - __half2float(h));
    // zero fp16 mu mirror
    g_muAh[(size_t)n * 384 + f] = __float2half(0.0f);
    g_muAh[(size_t)n * 384 + 128 + f] = __float2half(0.0f);
    g_muAh[(size_t)n * 384 + 256 + f] = __float2half(0.0f);
}

// ---------------- edge aggregation (deterministic, gather-side) ----------------
#define MAXD 512
__global__ void __launch_bounds__(128) k_edge() {
    int i = blockIdx.x;
    int f = threadIdx.x;
    int s0 = g_start[i], s1 = g_start[i + 1];
    int L = s1 - s0;
    __shared__ int se[MAXD];
    __shared__ int ord[MAXD];
    bool srt = (L <= MAXD);
    if (srt && L > 0) {
        for (int a = f; a < L; a += 128) se[a] = g_eo[s0 + a];
        __syncthreads();
        for (int a = f; a < L; a += 128) {
            int my = se[a];
            int r = 0;
            for (int b = 0; b < L; b++) r += (se[b] < my);
            ord[r] = a;
        }
        __syncthreads();
    }
    float aq = 0.0f, m0 = 0.0f, m1 = 0.0f, m2 = 0.0f;
    for (int a = 0; a < L; a++) {
        int slot = s0 + (srt ? ord[a] : a);
        int j = g_js[slot];
        float d0 = g_dir[3 * slot + 0];
        float d1 = g_dir[3 * slot + 1];
        float d2 = g_dir[3 * slot + 2];
        size_t fbx = (size_t)slot * 384;
        float fq = __half2float(g_filth[fbx + f]);
        float fR = __half2float(g_filth[fbx + 128 + f]);
        float fM = __half2float(g_filth[fbx + 256 + f]);
        size_t xb = (size_t)j * 384;
        float xq = __half2float(g_xh[xb + f]);
        float xR = __half2float(g_xh[xb + 128 + f]);
        float xM = __half2float(g_xh[xb + 256 + f]);
        float mj0 = __half2float(g_muAh[xb + f]);
        float mj1 = __half2float(g_muAh[xb + 128 + f]);
        float mj2 = __half2float(g_muAh[xb + 256 + f]);
        aq += fq * xq;
        float tR = fR * xR, tM = fM * xM;
        m0 += tR * d0 + tM * mj0;
        m1 += tR * d1 + tM * mj1;
        m2 += tR * d2 + tM * mj2;
    }
    size_t mb_ = (size_t)i * 384;
    g_q[(size_t)i * 128 + f] += aq;
    float b0 = g_muA[mb_ + f] + m0;
    float b1 = g_muA[mb_ + 128 + f] + m1;
    float b2 = g_muA[mb_ + 256 + f] + m2;
    g_muB[mb_ + f] = b0;
    g_muB[mb_ + 128 + f] = b1;
    g_muB[mb_ + 256 + f] = b2;
    size_t hb = (size_t)i * 768;
    __half h0 = __float2half(b0);
    __half h1 = __float2half(b1);
    __half h2 = __float2half(b2);
    g_muBhl[hb + f] = h0;
    g_muBhl[hb + 128 + f] = __float2half(b0 - __half2float(h0));
    g_muBhl[hb + 256 + f] = h1;
    g_muBhl[hb + 384 + f] = __float2half(b1 - __half2float(h1));
    g_muBhl[hb + 512 + f] = h2;
    g_muBhl[hb + 640 + f] = __float2half(b2 - __half2float(h2));
}

// ---------------- mixing elementwise ----------------
__global__ void k_ctx() {
    int n = blockIdx.x;
    int f = threadIdx.x;
    size_t mmb = (size_t)n * 768;
    float v0 = __half2float(g_mm[mmb + f]);
    float v1 = __half2float(g_mm[mmb + 256 + f]);
    float v2 = __half2float(g_mm[mmb + 512 + f]);
    float w0 = __half2float(g_mm[mmb + 128 + f]);
    float w1 = __half2float(g_mm[mmb + 384 + f]);
    float w2 = __half2float(g_mm[mmb + 640 + f]);
    float vn = sqrtf(v0 * v0 + v1 * v1 + v2 * v2 + 1e-8f);
    float s = v0 * w0 + v1 * w1 + v2 * w2;
    float qv = g_q[(size_t)n * 128 + f];
    size_t cb = (size_t)n * 512;
    __half qh = __float2half(qv);
    __half vh = __float2half(vn);
    g_ctxhl[cb + f] = qh;
    g_ctxhl[cb + 128 + f] = vh;
    g_ctxhl[cb + 256 + f] = __float2half(qv - __half2float(qh));
    g_ctxhl[cb + 384 + f] = __float2half(vn - __half2float(vh));
    g_s[(size_t)n * 128 + f] = s;
}

__global__ void k_update() {
    int n = blockIdx.x;
    int f = threadIdx.x;
    size_t xb = (size_t)n * 384;
    float dq  = g_x[xb + f];
    float dmc = g_x[xb + 128 + f];
    float dqm = g_x[xb + 256 + f];
    float qn = g_q[(size_t)n * 128 + f] + dq + dqm * g_s[(size_t)n * 128 + f];
    g_q[(size_t)n * 128 + f] = qn;
    __half qh = __float2half(qn);
    g_qhl[(size_t)n * 256 + f] = qh;
    g_qhl[(size_t)n * 256 + 128 + f] = __float2half(qn - __half2float(qh));
    size_t mmb = (size_t)n * 768;
    float a0 = g_muB[xb + f]       + dmc * __half2float(g_mm[mmb + 128 + f]);
    float a1 = g_muB[xb + 128 + f] + dmc * __half2float(g_mm[mmb + 384 + f]);
    float a2 = g_muB[xb + 256 + f] + dmc * __half2float(g_mm[mmb + 640 + f]);
    g_muA[xb + f] = a0;
    g_muA[xb + 128 + f] = a1;
    g_muA[xb + 256 + f] = a2;
    g_muAh[xb + f] = __float2half(a0);
    g_muAh[xb + 128 + f] = __float2half(a1);
    g_muAh[xb + 256 + f] = __float2half(a2);
}

// ---------------- launcher ----------------
extern "C" void kernel_launch(void* const* d_in, const int* in_sizes, int n_in,
                              void* d_out, int out_size) {
    const int*   z     = (const int*)d_in[0];
    const float* pos   = (const float*)d_in[1];
    const int*   idx_i = (const int*)d_in[2];
    const int*   idx_j = (const int*)d_in[3];
    const float* emb   = (const float*)d_in[4];
    const float* fW    = (const float*)d_in[5];
    const float* fb    = (const float*)d_in[6];
    const float* iW1   = (const float*)d_in[7];
    const float* ib1   = (const float*)d_in[8];
    const float* iW2   = (const float*)d_in[9];
    const float* ib2   = (const float*)d_in[10];
    const float* mWmix = (const float*)d_in[11];
    const float* mW1   = (const float*)d_in[12];
    const float* mb1   = (const float*)d_in[13];
    const float* mW2   = (const float*)d_in[14];
    const float* mb2   = (const float*)d_in[15];
    float* out = (float*)d_out;

    cudaFuncSetAttribute(k_wgemm, cudaFuncAttributeMaxDynamicSharedMemorySize, SMEM_WG);

    void *p_cnt, *p_muA, *p_q, *p_x, *p_xh, *p_mm, *p_filth;
    void *p_qhl, *p_hhl, *p_ctxhl, *p_muBhl, *p_phiHL, *p_fWXhl;
    void *p_WT1, *p_WT2, *p_WTmix, *p_WTm1, *p_WTm2;
    cudaGetSymbolAddress(&p_cnt, g_cnt);
    cudaGetSymbolAddress(&p_muA, g_muA);
    cudaGetSymbolAddress(&p_q, g_q);
    cudaGetSymbolAddress(&p_x, g_x);
    cudaGetSymbolAddress(&p_xh, g_xh);
    cudaGetSymbolAddress(&p_mm, g_mm);
    cudaGetSymbolAddress(&p_filth, g_filth);
    cudaGetSymbolAddress(&p_qhl, g_qhl);
    cudaGetSymbolAddress(&p_hhl, g_hhl);
    cudaGetSymbolAddress(&p_ctxhl, g_ctxhl);
    cudaGetSymbolAddress(&p_muBhl, g_muBhl);
    cudaGetSymbolAddress(&p_phiHL, g_phiHL);
    cudaGetSymbolAddress(&p_fWXhl, g_fWXhl);
    cudaGetSymbolAddress(&p_WT1, g_WT1);
    cudaGetSymbolAddress(&p_WT2, g_WT2);
    cudaGetSymbolAddress(&p_WTmix, g_WTmix);
    cudaGetSymbolAddress(&p_WTm1, g_WTm1);
    cudaGetSymbolAddress(&p_WTm2, g_WTm2);

    const __half* qhl = (const __half*)p_qhl;
    const __half* hhl = (const __half*)p_hhl;
    const __half* ctxhl = (const __half*)p_ctxhl;
    const __half* muBhl = (const __half*)p_muBhl;
    const __half* phiHL = (const __half*)p_phiHL;

    int ga = (NA + 127) / 128;       // 196
    int gm = (NA * 3 + 127) / 128;   // 586
    int ge = (NE + 127) / 128;       // 1563

    // ---- prep, ordered so the flagship GEMM is launch #6 (ncu -s 5 -c 1) ----
    cudaMemsetAsync(p_cnt, 0, NA * sizeof(int));                       // 1
    cudaMemsetAsync(p_muA, 0, (size_t)NA * 384 * sizeof(float));       // 2
    k_init_q<<<NA, 128>>>(z, emb);                                     // 3
    k_wsplit<<<dim3((128 * 128 + 255) / 256, 3), 256>>>(iW1, (__half*)p_WT1, 128, 128);   // 4
    k_wsplit<<<dim3((128 * 384 + 255) / 256, 3), 256>>>(iW2, (__half*)p_WT2, 128, 384);   // 5
    // H1(t=0): launch #6 -> profiled
    k_wgemm<<<dim3(ga, 2), 128, SMEM_WG>>>(
        qhl, (const __half*)p_WT1, ib1, nullptr, (__half*)p_hhl, NA, 256, 128, 1, 1);
    k_wsplit<<<dim3((128 * 256 + 255) / 256, 3), 256>>>(mWmix, (__half*)p_WTmix, 128, 256);
    k_wsplit<<<dim3((256 * 128 + 255) / 256, 3), 256>>>(mW1, (__half*)p_WTm1, 256, 128);
    k_wsplit<<<dim3((128 * 384 + 255) / 256, 3), 256>>>(mW2, (__half*)p_WTm2, 128, 384);
    k_fwx<<<(1152 + 127) / 128, 128>>>(fW, fb);
    k_count<<<(NE + 255) / 256, 256>>>(idx_i);
    k_scan<<<1, 1024>>>();
    k_build<<<(NE + 127) / 128, 128>>>(pos, idx_i, idx_j);

    for (int t = 0; t < 3; t++) {
        if (t > 0) {
            k_wgemm<<<dim3(ga, 2), 128, SMEM_WG>>>(
                qhl, (const __half*)p_WT1 + (size_t)t * 128 * 256,
                ib1 + t * 128, nullptr, (__half*)p_hhl, NA, 256, 128, 1, 1);
        }
        // X = H1 @ iW2 + ib2 -> g_xh (fp16 plain)
        k_wgemm<<<dim3(ga, 6), 128, SMEM_WG>>>(
            hhl, (const __half*)p_WT2 + (size_t)t * 384 * 256,
            ib2 + t * 384, nullptr, (__half*)p_xh, NA, 256, 384, 2, 0);
        // FILT = phi' @ fWX'^T -> g_filth (fp16 plain)
        k_wgemm<<<dim3(ge, 6), 128, SMEM_WG>>>(
            phiHL, (const __half*)p_fWXhl + (size_t)t * 384 * 64,
            nullptr, nullptr, (__half*)p_filth, NE, 64, 384, 2, 0);
        // edge aggregation
        k_edge<<<NA, 128>>>();
        // MUMIX = muB @ mWmix -> g_mm (fp16 plain)
        k_wgemm<<<dim3(gm, 4), 128, SMEM_WG>>>(
            muBhl, (const __half*)p_WTmix + (size_t)t * 256 * 256,
            nullptr, nullptr, (__half*)p_mm, NA * 3, 256, 256, 2, 0);
        k_ctx<<<NA, 128>>>();
        // H2 = silu(ctx @ mW1 + mb1) -> hhl   (K=512 packed)
        k_wgemm<<<dim3(ga, 2), 128, SMEM_WG>>>(
            ctxhl, (const __half*)p_WTm1 + (size_t)t * 128 * 512,
            mb1 + t * 128, nullptr, (__half*)p_hhl, NA, 512, 128, 1, 1);
        // X2 = H2 @ mW2 + mb2 -> g_x (fp32)
        k_wgemm<<<dim3(ga, 6), 128, SMEM_WG>>>(
            hhl, (const __half*)p_WTm2 + (size_t)t * 384 * 256,
            mb2 + t * 384, (float*)p_x, nullptr, NA, 256, 384, 0, 0);
        k_update<<<NA, 128>>>();
    }

    cudaMemcpyAsync(out, p_q, (size_t)NA * 128 * sizeof(float), cudaMemcpyDeviceToDevice);
    cudaMemcpyAsync(out + (size_t)NA * 128, p_muA, (size_t)NA * 384 * sizeof(float),
                    cudaMemcpyDeviceToDevice);
}